// round 2
// baseline (speedup 1.0000x reference)
#include <cuda_runtime.h>
#include <math.h>

#define NN 50000
#define EE 800000
#define HD 256
#define NH 4
#define DH 64

// ---- static scratch (no allocations allowed) ----
__device__ float g_q[(size_t)NN * HD];
__device__ float g_k[(size_t)NN * HD];
__device__ float g_v[(size_t)NN * HD];
__device__ float g_skip[(size_t)NN * HD];
__device__ float g_agg[(size_t)NN * HD];
__device__ float g_e[(size_t)EE * NH];
__device__ float g_m[(size_t)NN * NH];
__device__ float g_den[(size_t)NN * NH];

// ---------------------------------------------------------------------------
// init: agg = 0, m = -inf, den = 0
// ---------------------------------------------------------------------------
__global__ void init_kernel(int n) {
    int i = blockIdx.x * blockDim.x + threadIdx.x;
    if (i < n * HD) g_agg[i] = 0.0f;
    if (i < n * NH) {
        g_m[i] = -3.402823466e38f;
        g_den[i] = 0.0f;
    }
}

// ---------------------------------------------------------------------------
// 4 projections as one batched tiled SGEMM (NT): C = feat @ W^T + b
// BM=64, BN=64, BK=16, 256 threads, 4x4 per thread.
// blockIdx.z selects {q,k,v,skip}.
// ---------------------------------------------------------------------------
__global__ __launch_bounds__(256) void proj_gemm(
    const float* __restrict__ feat,
    const float* __restrict__ Wq, const float* __restrict__ bq,
    const float* __restrict__ Wk, const float* __restrict__ bk,
    const float* __restrict__ Wv, const float* __restrict__ bv,
    const float* __restrict__ Ws, const float* __restrict__ bs,
    int M)
{
    const int BM = 64, BN = 64, BK = 16;
    __shared__ float As[BK][BM];
    __shared__ float Bs[BK][BN];

    const float* W;
    const float* bias;
    float* C;
    switch (blockIdx.z) {
        case 0:  W = Wq; bias = bq; C = g_q;    break;
        case 1:  W = Wk; bias = bk; C = g_k;    break;
        case 2:  W = Wv; bias = bv; C = g_v;    break;
        default: W = Ws; bias = bs; C = g_skip; break;
    }

    int tid  = threadIdx.x;
    int bm   = blockIdx.y * BM;
    int bn   = blockIdx.x * BN;
    int lrow = tid >> 2;        // 0..63
    int lc4  = (tid & 3) * 4;   // 0,4,8,12
    int ty   = tid >> 4;        // 0..15
    int tx   = tid & 15;        // 0..15

    float acc[4][4] = {};

    for (int kk = 0; kk < 256; kk += BK) {
        int arow = bm + lrow;
        float4 a4 = (arow < M)
            ? *(const float4*)(feat + (size_t)arow * 256 + kk + lc4)
            : make_float4(0.f, 0.f, 0.f, 0.f);
        As[lc4 + 0][lrow] = a4.x;
        As[lc4 + 1][lrow] = a4.y;
        As[lc4 + 2][lrow] = a4.z;
        As[lc4 + 3][lrow] = a4.w;

        float4 b4 = *(const float4*)(W + (size_t)(bn + lrow) * 256 + kk + lc4);
        Bs[lc4 + 0][lrow] = b4.x;
        Bs[lc4 + 1][lrow] = b4.y;
        Bs[lc4 + 2][lrow] = b4.z;
        Bs[lc4 + 3][lrow] = b4.w;

        __syncthreads();

        #pragma unroll
        for (int k = 0; k < BK; k++) {
            float4 av = *(const float4*)&As[k][ty * 4];
            float4 bv4 = *(const float4*)&Bs[k][tx * 4];
            float a[4] = {av.x, av.y, av.z, av.w};
            float b[4] = {bv4.x, bv4.y, bv4.z, bv4.w};
            #pragma unroll
            for (int i = 0; i < 4; i++)
                #pragma unroll
                for (int j = 0; j < 4; j++)
                    acc[i][j] += a[i] * b[j];
        }
        __syncthreads();
    }

    int row0 = bm + ty * 4;
    int col0 = bn + tx * 4;
    #pragma unroll
    for (int i = 0; i < 4; i++) {
        int r = row0 + i;
        if (r < M) {
            float4 o;
            o.x = acc[i][0] + bias[col0 + 0];
            o.y = acc[i][1] + bias[col0 + 1];
            o.z = acc[i][2] + bias[col0 + 2];
            o.w = acc[i][3] + bias[col0 + 3];
            *(float4*)(C + (size_t)r * 256 + col0) = o;
        }
    }
}

// ---------------------------------------------------------------------------
// per-edge scores: e[e,h] = 0.125 * dot(q[src], k[dst]) per head
// one warp per edge; lanes [8h, 8h+8) own head h (8 floats each)
// ---------------------------------------------------------------------------
__global__ __launch_bounds__(256) void edge_scores(
    const int* __restrict__ src, const int* __restrict__ dst, int E)
{
    int gw   = (int)((blockIdx.x * 256u + threadIdx.x) >> 5);
    int lane = threadIdx.x & 31;
    if (gw >= E) return;
    int s = src[gw], d = dst[gw];
    const float4* qr = (const float4*)(g_q + (size_t)s * HD);
    const float4* kr = (const float4*)(g_k + (size_t)d * HD);
    float4 q0 = qr[lane * 2], q1 = qr[lane * 2 + 1];
    float4 k0 = kr[lane * 2], k1 = kr[lane * 2 + 1];
    float p = q0.x * k0.x + q0.y * k0.y + q0.z * k0.z + q0.w * k0.w
            + q1.x * k1.x + q1.y * k1.y + q1.z * k1.z + q1.w * k1.w;
    p += __shfl_xor_sync(0xffffffffu, p, 4);
    p += __shfl_xor_sync(0xffffffffu, p, 2);
    p += __shfl_xor_sync(0xffffffffu, p, 1);
    if ((lane & 7) == 0)
        g_e[(size_t)gw * NH + (lane >> 3)] = p * 0.125f;
}

// ---------------------------------------------------------------------------
// segment max over dst (float atomic max via int ordering trick)
// ---------------------------------------------------------------------------
__global__ void edge_max(const int* __restrict__ dst, int EH) {
    int i = blockIdx.x * blockDim.x + threadIdx.x;
    if (i >= EH) return;
    int edge = i >> 2, h = i & 3;
    float v = g_e[i];
    float* addr = &g_m[(size_t)dst[edge] * NH + h];
    if (v >= 0.0f) atomicMax((int*)addr, __float_as_int(v));
    else           atomicMin((unsigned int*)addr, (unsigned int)__float_as_int(v));
}

// ---------------------------------------------------------------------------
// ex = exp(e - m[dst]); denom[dst] += ex
// ---------------------------------------------------------------------------
__global__ void edge_exp(const int* __restrict__ dst, int EH) {
    int i = blockIdx.x * blockDim.x + threadIdx.x;
    if (i >= EH) return;
    int edge = i >> 2, h = i & 3;
    int d = dst[edge];
    float ex = __expf(g_e[i] - g_m[(size_t)d * NH + h]);
    g_e[i] = ex;
    atomicAdd(&g_den[(size_t)d * NH + h], ex);
}

// ---------------------------------------------------------------------------
// agg[dst] += (ex/denom[dst]) * v[src]   (one warp per edge, float4 red)
// ---------------------------------------------------------------------------
__global__ __launch_bounds__(256) void edge_agg(
    const int* __restrict__ src, const int* __restrict__ dst, int E)
{
    int gw   = (int)((blockIdx.x * 256u + threadIdx.x) >> 5);
    int lane = threadIdx.x & 31;
    if (gw >= E) return;
    int s = src[gw], d = dst[gw];
    int h = lane >> 3;
    float sa = g_e[(size_t)gw * NH + h] / g_den[(size_t)d * NH + h];
    const float4* vr = (const float4*)(g_v + (size_t)s * HD);
    float4 v0 = vr[lane * 2], v1 = vr[lane * 2 + 1];
    float4* ar = (float4*)(g_agg + (size_t)d * HD);
    float4 o0 = make_float4(sa * v0.x, sa * v0.y, sa * v0.z, sa * v0.w);
    float4 o1 = make_float4(sa * v1.x, sa * v1.y, sa * v1.z, sa * v1.w);
    atomicAdd(ar + lane * 2,     o0);
    atomicAdd(ar + lane * 2 + 1, o1);
}

// ---------------------------------------------------------------------------
// epilogue: gated skip + layernorm + PReLU.  one warp per node.
// ---------------------------------------------------------------------------
__global__ __launch_bounds__(256) void epilogue(
    const float* __restrict__ Wg, const float* __restrict__ bg,
    const float* __restrict__ lnw, const float* __restrict__ lnb,
    const float* __restrict__ prelu_a, float* __restrict__ out, int N)
{
    int w    = (int)((blockIdx.x * 256u + threadIdx.x) >> 5);
    int lane = threadIdx.x & 31;
    if (w >= N) return;

    const float4* skp = (const float4*)(g_skip + (size_t)w * HD);
    const float4* agp = (const float4*)(g_agg  + (size_t)w * HD);
    float4 s0 = skp[lane * 2], s1 = skp[lane * 2 + 1];
    float4 r0 = agp[lane * 2], r1 = agp[lane * 2 + 1];
    float sk[8] = {s0.x, s0.y, s0.z, s0.w, s1.x, s1.y, s1.z, s1.w};
    float rs[8] = {r0.x, r0.y, r0.z, r0.w, r1.x, r1.y, r1.z, r1.w};

    // gate = sigmoid([skip; rst; skip-rst] . Wg + bg)
    float gp = 0.0f;
    #pragma unroll
    for (int i = 0; i < 8; i++) {
        int c = lane * 8 + i;
        gp += sk[i] * Wg[c] + rs[i] * Wg[256 + c] + (sk[i] - rs[i]) * Wg[512 + c];
    }
    #pragma unroll
    for (int m = 16; m >= 1; m >>= 1) gp += __shfl_xor_sync(0xffffffffu, gp, m);
    float g = 1.0f / (1.0f + expf(-(gp + bg[0])));

    float x[8];
    float sum = 0.0f;
    #pragma unroll
    for (int i = 0; i < 8; i++) {
        x[i] = g * sk[i] + (1.0f - g) * rs[i];
        sum += x[i];
    }
    #pragma unroll
    for (int m = 16; m >= 1; m >>= 1) sum += __shfl_xor_sync(0xffffffffu, sum, m);
    float mu = sum * (1.0f / 256.0f);

    float vs = 0.0f;
    #pragma unroll
    for (int i = 0; i < 8; i++) {
        float dd = x[i] - mu;
        vs += dd * dd;
    }
    #pragma unroll
    for (int m = 16; m >= 1; m >>= 1) vs += __shfl_xor_sync(0xffffffffu, vs, m);
    float rstd = rsqrtf(vs * (1.0f / 256.0f) + 1e-5f);

    float a = *prelu_a;
    float o[8];
    #pragma unroll
    for (int i = 0; i < 8; i++) {
        int c = lane * 8 + i;
        float y = (x[i] - mu) * rstd * lnw[c] + lnb[c];
        o[i] = (y >= 0.0f) ? y : a * y;
    }
    float4* op = (float4*)(out + (size_t)w * HD);
    op[lane * 2]     = make_float4(o[0], o[1], o[2], o[3]);
    op[lane * 2 + 1] = make_float4(o[4], o[5], o[6], o[7]);
}

// ---------------------------------------------------------------------------
extern "C" void kernel_launch(void* const* d_in, const int* in_sizes, int n_in,
                              void* d_out, int out_size)
{
    const float* feat = (const float*)d_in[0];
    const int*   src  = (const int*)d_in[1];
    const int*   dst  = (const int*)d_in[2];
    const float* Wq = (const float*)d_in[3];  const float* bq = (const float*)d_in[4];
    const float* Wk = (const float*)d_in[5];  const float* bk = (const float*)d_in[6];
    const float* Wv = (const float*)d_in[7];  const float* bv = (const float*)d_in[8];
    const float* Ws = (const float*)d_in[9];  const float* bs = (const float*)d_in[10];
    const float* Wg = (const float*)d_in[11]; const float* bg = (const float*)d_in[12];
    const float* lnw = (const float*)d_in[13];
    const float* lnb = (const float*)d_in[14];
    const float* pa  = (const float*)d_in[15];
    float* out = (float*)d_out;

    int M = in_sizes[0] / HD;   // 50000
    int E = in_sizes[1];        // 800000
    if (M > NN) M = NN;
    if (E > EE) E = EE;

    init_kernel<<<(M * HD + 255) / 256, 256>>>(M);

    dim3 gg(HD / 64, (M + 63) / 64, 4);
    proj_gemm<<<gg, 256>>>(feat, Wq, bq, Wk, bk, Wv, bv, Ws, bs, M);

    edge_scores<<<(E + 7) / 8, 256>>>(src, dst, E);
    edge_max<<<(E * NH + 255) / 256, 256>>>(dst, E * NH);
    edge_exp<<<(E * NH + 255) / 256, 256>>>(dst, E * NH);
    edge_agg<<<(E + 7) / 8, 256>>>(src, dst, E);

    // one warp per node: 8 warps (256 threads) per block
    epilogue<<<(M + 7) / 8, 256>>>(Wg, bg, lnw, lnb, pa, out, M);
}

// round 3
// speedup vs baseline: 1.5371x; 1.5371x over previous
#include <cuda_runtime.h>
#include <math.h>
#include <stdint.h>

#define NN 50000
#define EE 800000
#define HD 256
#define NH 4
#define DH 64

// ---- static scratch (no allocations allowed) ----
__device__ float g_q[(size_t)NN * HD];
__device__ float g_k[(size_t)NN * HD];
__device__ float g_v[(size_t)NN * HD];
__device__ float g_skip[(size_t)NN * HD];
__device__ float g_agg[(size_t)NN * HD];
__device__ float g_e[(size_t)EE * NH];
__device__ float g_m[(size_t)NN * NH];
__device__ float g_den[(size_t)NN * NH];

// ---------------------------------------------------------------------------
// init: agg = 0, m = -inf, den = 0
// ---------------------------------------------------------------------------
__global__ void init_kernel(int n) {
    int i = blockIdx.x * blockDim.x + threadIdx.x;
    if (i < n * HD) g_agg[i] = 0.0f;
    if (i < n * NH) {
        g_m[i] = -3.402823466e38f;
        g_den[i] = 0.0f;
    }
}

// ---------------------------------------------------------------------------
// tf32 helpers
// ---------------------------------------------------------------------------
__device__ __forceinline__ uint32_t f2tf32(float x) {
    uint32_t r;
    asm("cvt.rna.tf32.f32 %0, %1;" : "=r"(r) : "f"(x));
    return r;
}

__device__ __forceinline__ void mma_tf32(float c[4],
    uint32_t a0, uint32_t a1, uint32_t a2, uint32_t a3,
    uint32_t b0, uint32_t b1)
{
    asm volatile(
        "mma.sync.aligned.m16n8k8.row.col.f32.tf32.tf32.f32 "
        "{%0,%1,%2,%3}, {%4,%5,%6,%7}, {%8,%9}, {%0,%1,%2,%3};\n"
        : "+f"(c[0]), "+f"(c[1]), "+f"(c[2]), "+f"(c[3])
        : "r"(a0), "r"(a1), "r"(a2), "r"(a3), "r"(b0), "r"(b1));
}

// ---------------------------------------------------------------------------
// 4 projections, tf32 tensor-core GEMM (NT): C = feat @ W^T + b
// BM=128, BN=64, BK=16, 256 threads (8 warps, 4x2), warp tile 32x32.
// SMEM stored [k][m]/[k][n] with stride 136/72 (== 8 mod 32: conflict-free
// fragment loads). blockIdx.z selects {q,k,v,skip}.
// ---------------------------------------------------------------------------
#define GBM 128
#define GBN 64
#define GBK 16
#define ASTR 136
#define BSTR 72

__global__ __launch_bounds__(256) void proj_gemm_tf32(
    const float* __restrict__ feat,
    const float* __restrict__ Wq, const float* __restrict__ bq,
    const float* __restrict__ Wk, const float* __restrict__ bk,
    const float* __restrict__ Wv, const float* __restrict__ bv,
    const float* __restrict__ Ws, const float* __restrict__ bs,
    int M)
{
    __shared__ uint32_t As[GBK][ASTR];
    __shared__ uint32_t Bs[GBK][BSTR];

    const float* W;
    const float* bias;
    float* C;
    switch (blockIdx.z) {
        case 0:  W = Wq; bias = bq; C = g_q;    break;
        case 1:  W = Wk; bias = bk; C = g_k;    break;
        case 2:  W = Wv; bias = bv; C = g_v;    break;
        default: W = Ws; bias = bs; C = g_skip; break;
    }

    const int tid   = threadIdx.x;
    const int lane  = tid & 31;
    const int warp  = tid >> 5;
    const int warpM = warp & 3;   // 0..3 (32 rows each)
    const int warpN = warp >> 2;  // 0..1 (32 cols each)
    const int bm = blockIdx.y * GBM;
    const int bn = blockIdx.x * GBN;

    const int arow = tid >> 2;        // 0..63
    const int acol = (tid & 3) * 4;   // 0,4,8,12

    const int gid = lane >> 2;   // groupID 0..7
    const int tig = lane & 3;    // threadID_in_group 0..3

    float acc[2][4][4] = {};

    for (int kk = 0; kk < 256; kk += GBK) {
        // A tile: rows arow, arow+64
        #pragma unroll
        for (int j = 0; j < 2; j++) {
            int row = bm + arow + j * 64;
            float4 a4 = (row < M)
                ? *(const float4*)(feat + (size_t)row * 256 + kk + acol)
                : make_float4(0.f, 0.f, 0.f, 0.f);
            As[acol + 0][arow + j * 64] = f2tf32(a4.x);
            As[acol + 1][arow + j * 64] = f2tf32(a4.y);
            As[acol + 2][arow + j * 64] = f2tf32(a4.z);
            As[acol + 3][arow + j * 64] = f2tf32(a4.w);
        }
        // B tile: 64 rows of W
        {
            float4 b4 = *(const float4*)(W + (size_t)(bn + arow) * 256 + kk + acol);
            Bs[acol + 0][arow] = f2tf32(b4.x);
            Bs[acol + 1][arow] = f2tf32(b4.y);
            Bs[acol + 2][arow] = f2tf32(b4.z);
            Bs[acol + 3][arow] = f2tf32(b4.w);
        }
        __syncthreads();

        #pragma unroll
        for (int ks = 0; ks < GBK; ks += 8) {
            uint32_t af[2][4];
            #pragma unroll
            for (int mt = 0; mt < 2; mt++) {
                int r = warpM * 32 + mt * 16 + gid;
                af[mt][0] = As[ks + tig    ][r];
                af[mt][1] = As[ks + tig    ][r + 8];
                af[mt][2] = As[ks + tig + 4][r];
                af[mt][3] = As[ks + tig + 4][r + 8];
            }
            uint32_t bf[4][2];
            #pragma unroll
            for (int nt = 0; nt < 4; nt++) {
                int nidx = warpN * 32 + nt * 8 + gid;
                bf[nt][0] = Bs[ks + tig    ][nidx];
                bf[nt][1] = Bs[ks + tig + 4][nidx];
            }
            #pragma unroll
            for (int mt = 0; mt < 2; mt++)
                #pragma unroll
                for (int nt = 0; nt < 4; nt++)
                    mma_tf32(acc[mt][nt],
                             af[mt][0], af[mt][1], af[mt][2], af[mt][3],
                             bf[nt][0], bf[nt][1]);
        }
        __syncthreads();
    }

    // epilogue: add bias, store
    #pragma unroll
    for (int mt = 0; mt < 2; mt++) {
        int row = bm + warpM * 32 + mt * 16 + gid;
        #pragma unroll
        for (int nt = 0; nt < 4; nt++) {
            int col = bn + warpN * 32 + nt * 8 + tig * 2;
            float b0 = bias[col], b1 = bias[col + 1];
            if (row < M) {
                float2 o = make_float2(acc[mt][nt][0] + b0, acc[mt][nt][1] + b1);
                *(float2*)(C + (size_t)row * 256 + col) = o;
            }
            if (row + 8 < M) {
                float2 o = make_float2(acc[mt][nt][2] + b0, acc[mt][nt][3] + b1);
                *(float2*)(C + (size_t)(row + 8) * 256 + col) = o;
            }
        }
    }
}

// ---------------------------------------------------------------------------
// per-edge scores + fused segment max:
// e[e,h] = 0.125 * dot(q[src], k[dst]); atomicMax into g_m
// one warp per edge; lanes [8h, 8h+8) own head h
// ---------------------------------------------------------------------------
__global__ __launch_bounds__(256) void edge_scores(
    const int* __restrict__ src, const int* __restrict__ dst, int E)
{
    int gw   = (int)((blockIdx.x * 256u + threadIdx.x) >> 5);
    int lane = threadIdx.x & 31;
    if (gw >= E) return;
    int s = src[gw], d = dst[gw];
    const float4* qr = (const float4*)(g_q + (size_t)s * HD);
    const float4* kr = (const float4*)(g_k + (size_t)d * HD);
    float4 q0 = qr[lane * 2], q1 = qr[lane * 2 + 1];
    float4 k0 = kr[lane * 2], k1 = kr[lane * 2 + 1];
    float p = q0.x * k0.x + q0.y * k0.y + q0.z * k0.z + q0.w * k0.w
            + q1.x * k1.x + q1.y * k1.y + q1.z * k1.z + q1.w * k1.w;
    p += __shfl_xor_sync(0xffffffffu, p, 4);
    p += __shfl_xor_sync(0xffffffffu, p, 2);
    p += __shfl_xor_sync(0xffffffffu, p, 1);
    if ((lane & 7) == 0) {
        int h = lane >> 3;
        float e = p * 0.125f;
        g_e[(size_t)gw * NH + h] = e;
        float* addr = &g_m[(size_t)d * NH + h];
        if (e >= 0.0f) atomicMax((int*)addr, __float_as_int(e));
        else           atomicMin((unsigned int*)addr, (unsigned int)__float_as_int(e));
    }
}

// ---------------------------------------------------------------------------
// ex = exp(e - m[dst]); denom[dst] += ex
// ---------------------------------------------------------------------------
__global__ void edge_exp(const int* __restrict__ dst, int EH) {
    int i = blockIdx.x * blockDim.x + threadIdx.x;
    if (i >= EH) return;
    int edge = i >> 2, h = i & 3;
    int d = dst[edge];
    float ex = __expf(g_e[i] - g_m[(size_t)d * NH + h]);
    g_e[i] = ex;
    atomicAdd(&g_den[(size_t)d * NH + h], ex);
}

// ---------------------------------------------------------------------------
// agg[dst] += (ex/denom[dst]) * v[src]   (one warp per edge, float4 red)
// ---------------------------------------------------------------------------
__global__ __launch_bounds__(256) void edge_agg(
    const int* __restrict__ src, const int* __restrict__ dst, int E)
{
    int gw   = (int)((blockIdx.x * 256u + threadIdx.x) >> 5);
    int lane = threadIdx.x & 31;
    if (gw >= E) return;
    int s = src[gw], d = dst[gw];
    int h = lane >> 3;
    float sa = g_e[(size_t)gw * NH + h] / g_den[(size_t)d * NH + h];
    const float4* vr = (const float4*)(g_v + (size_t)s * HD);
    float4 v0 = vr[lane * 2], v1 = vr[lane * 2 + 1];
    float4* ar = (float4*)(g_agg + (size_t)d * HD);
    float4 o0 = make_float4(sa * v0.x, sa * v0.y, sa * v0.z, sa * v0.w);
    float4 o1 = make_float4(sa * v1.x, sa * v1.y, sa * v1.z, sa * v1.w);
    atomicAdd(ar + lane * 2,     o0);
    atomicAdd(ar + lane * 2 + 1, o1);
}

// ---------------------------------------------------------------------------
// epilogue: gated skip + layernorm + PReLU.  one warp per node.
// ---------------------------------------------------------------------------
__global__ __launch_bounds__(256) void epilogue(
    const float* __restrict__ Wg, const float* __restrict__ bg,
    const float* __restrict__ lnw, const float* __restrict__ lnb,
    const float* __restrict__ prelu_a, float* __restrict__ out, int N)
{
    int w    = (int)((blockIdx.x * 256u + threadIdx.x) >> 5);
    int lane = threadIdx.x & 31;
    if (w >= N) return;

    const float4* skp = (const float4*)(g_skip + (size_t)w * HD);
    const float4* agp = (const float4*)(g_agg  + (size_t)w * HD);
    float4 s0 = skp[lane * 2], s1 = skp[lane * 2 + 1];
    float4 r0 = agp[lane * 2], r1 = agp[lane * 2 + 1];
    float sk[8] = {s0.x, s0.y, s0.z, s0.w, s1.x, s1.y, s1.z, s1.w};
    float rs[8] = {r0.x, r0.y, r0.z, r0.w, r1.x, r1.y, r1.z, r1.w};

    // gate = sigmoid([skip; rst; skip-rst] . Wg + bg)
    float gp = 0.0f;
    #pragma unroll
    for (int i = 0; i < 8; i++) {
        int c = lane * 8 + i;
        gp += sk[i] * Wg[c] + rs[i] * Wg[256 + c] + (sk[i] - rs[i]) * Wg[512 + c];
    }
    #pragma unroll
    for (int m = 16; m >= 1; m >>= 1) gp += __shfl_xor_sync(0xffffffffu, gp, m);
    float g = 1.0f / (1.0f + expf(-(gp + bg[0])));

    float x[8];
    float sum = 0.0f;
    #pragma unroll
    for (int i = 0; i < 8; i++) {
        x[i] = g * sk[i] + (1.0f - g) * rs[i];
        sum += x[i];
    }
    #pragma unroll
    for (int m = 16; m >= 1; m >>= 1) sum += __shfl_xor_sync(0xffffffffu, sum, m);
    float mu = sum * (1.0f / 256.0f);

    float vs = 0.0f;
    #pragma unroll
    for (int i = 0; i < 8; i++) {
        float dd = x[i] - mu;
        vs += dd * dd;
    }
    #pragma unroll
    for (int m = 16; m >= 1; m >>= 1) vs += __shfl_xor_sync(0xffffffffu, vs, m);
    float rstd = rsqrtf(vs * (1.0f / 256.0f) + 1e-5f);

    float a = *prelu_a;
    float o[8];
    #pragma unroll
    for (int i = 0; i < 8; i++) {
        int c = lane * 8 + i;
        float y = (x[i] - mu) * rstd * lnw[c] + lnb[c];
        o[i] = (y >= 0.0f) ? y : a * y;
    }
    float4* op = (float4*)(out + (size_t)w * HD);
    op[lane * 2]     = make_float4(o[0], o[1], o[2], o[3]);
    op[lane * 2 + 1] = make_float4(o[4], o[5], o[6], o[7]);
}

// ---------------------------------------------------------------------------
extern "C" void kernel_launch(void* const* d_in, const int* in_sizes, int n_in,
                              void* d_out, int out_size)
{
    const float* feat = (const float*)d_in[0];
    const int*   src  = (const int*)d_in[1];
    const int*   dst  = (const int*)d_in[2];
    const float* Wq = (const float*)d_in[3];  const float* bq = (const float*)d_in[4];
    const float* Wk = (const float*)d_in[5];  const float* bk = (const float*)d_in[6];
    const float* Wv = (const float*)d_in[7];  const float* bv = (const float*)d_in[8];
    const float* Ws = (const float*)d_in[9];  const float* bs = (const float*)d_in[10];
    const float* Wg = (const float*)d_in[11]; const float* bg = (const float*)d_in[12];
    const float* lnw = (const float*)d_in[13];
    const float* lnb = (const float*)d_in[14];
    const float* pa  = (const float*)d_in[15];
    float* out = (float*)d_out;

    int M = in_sizes[0] / HD;   // 50000
    int E = in_sizes[1];        // 800000
    if (M > NN) M = NN;
    if (E > EE) E = EE;

    init_kernel<<<(M * HD + 255) / 256, 256>>>(M);

    dim3 gg(HD / GBN, (M + GBM - 1) / GBM, 4);
    proj_gemm_tf32<<<gg, 256>>>(feat, Wq, bq, Wk, bk, Wv, bv, Ws, bs, M);

    edge_scores<<<(E + 7) / 8, 256>>>(src, dst, E);
    edge_exp<<<(E * NH + 255) / 256, 256>>>(dst, E * NH);
    edge_agg<<<(E + 7) / 8, 256>>>(src, dst, E);

    epilogue<<<(M + 7) / 8, 256>>>(Wg, bg, lnw, lnb, pa, out, M);
}

// round 4
// speedup vs baseline: 2.0158x; 1.3114x over previous
#include <cuda_runtime.h>
#include <math.h>
#include <stdint.h>

#define NN 50000
#define EE 800000
#define HD 256
#define NH 4
#define DH 64

// ---- static scratch (no allocations allowed) ----
__device__ float g_q[(size_t)NN * HD];
__device__ float g_k[(size_t)NN * HD];
__device__ float g_v[(size_t)NN * HD];
__device__ float g_skip[(size_t)NN * HD];
__device__ int   g_deg[NN];
__device__ int   g_rowptr[NN + 1];
__device__ int   g_cursor[NN];
__device__ int   g_cidx[EE];

// ---------------------------------------------------------------------------
// CSR build: zero degree -> histogram -> scan -> scatter
// ---------------------------------------------------------------------------
__global__ void zero_deg(int n) {
    int i = blockIdx.x * blockDim.x + threadIdx.x;
    if (i < n) g_deg[i] = 0;
}

__global__ void hist_kernel(const int* __restrict__ dst, int E) {
    int i = blockIdx.x * blockDim.x + threadIdx.x;
    if (i < E) atomicAdd(&g_deg[dst[i]], 1);
}

// single block, 1024 threads: exclusive scan of g_deg -> g_rowptr, g_cursor
__global__ __launch_bounds__(1024) void scan_kernel(int n) {
    const int T = 1024;
    const int per = (NN + T - 1) / T;   // 49
    __shared__ int sm[T];
    int t = threadIdx.x;
    int base = t * per;
    int s = 0;
    for (int i = 0; i < per; i++) {
        int idx = base + i;
        if (idx < n) s += g_deg[idx];
    }
    sm[t] = s;
    __syncthreads();
    for (int off = 1; off < T; off <<= 1) {
        int v = (t >= off) ? sm[t - off] : 0;
        __syncthreads();
        sm[t] += v;
        __syncthreads();
    }
    int run = sm[t] - s;   // exclusive prefix for this chunk
    for (int i = 0; i < per; i++) {
        int idx = base + i;
        if (idx < n) {
            g_rowptr[idx] = run;
            g_cursor[idx] = run;
            run += g_deg[idx];
        }
    }
    if (t == T - 1) g_rowptr[n] = run;
}

__global__ void scatter_kernel(const int* __restrict__ src,
                               const int* __restrict__ dst, int E) {
    int i = blockIdx.x * blockDim.x + threadIdx.x;
    if (i < E) {
        int pos = atomicAdd(&g_cursor[dst[i]], 1);
        g_cidx[pos] = src[i];
    }
}

// ---------------------------------------------------------------------------
// tf32 helpers
// ---------------------------------------------------------------------------
__device__ __forceinline__ uint32_t f2tf32(float x) {
    uint32_t r;
    asm("cvt.rna.tf32.f32 %0, %1;" : "=r"(r) : "f"(x));
    return r;
}

__device__ __forceinline__ void mma_tf32(float c[4],
    uint32_t a0, uint32_t a1, uint32_t a2, uint32_t a3,
    uint32_t b0, uint32_t b1)
{
    asm volatile(
        "mma.sync.aligned.m16n8k8.row.col.f32.tf32.tf32.f32 "
        "{%0,%1,%2,%3}, {%4,%5,%6,%7}, {%8,%9}, {%0,%1,%2,%3};\n"
        : "+f"(c[0]), "+f"(c[1]), "+f"(c[2]), "+f"(c[3])
        : "r"(a0), "r"(a1), "r"(a2), "r"(a3), "r"(b0), "r"(b1));
}

// ---------------------------------------------------------------------------
// 4 projections, tf32 tensor-core GEMM (NT): C = feat @ W^T + b
// BM=128, BN=64, BK=16, 256 threads (8 warps, 4x2), warp tile 32x32.
// ---------------------------------------------------------------------------
#define GBM 128
#define GBN 64
#define GBK 16
#define ASTR 136
#define BSTR 72

__global__ __launch_bounds__(256) void proj_gemm_tf32(
    const float* __restrict__ feat,
    const float* __restrict__ Wq, const float* __restrict__ bq,
    const float* __restrict__ Wk, const float* __restrict__ bk,
    const float* __restrict__ Wv, const float* __restrict__ bv,
    const float* __restrict__ Ws, const float* __restrict__ bs,
    int M)
{
    __shared__ uint32_t As[GBK][ASTR];
    __shared__ uint32_t Bs[GBK][BSTR];

    const float* W;
    const float* bias;
    float* C;
    switch (blockIdx.z) {
        case 0:  W = Wq; bias = bq; C = g_q;    break;
        case 1:  W = Wk; bias = bk; C = g_k;    break;
        case 2:  W = Wv; bias = bv; C = g_v;    break;
        default: W = Ws; bias = bs; C = g_skip; break;
    }

    const int tid   = threadIdx.x;
    const int lane  = tid & 31;
    const int warp  = tid >> 5;
    const int warpM = warp & 3;
    const int warpN = warp >> 2;
    const int bm = blockIdx.y * GBM;
    const int bn = blockIdx.x * GBN;

    const int arow = tid >> 2;
    const int acol = (tid & 3) * 4;

    const int gid = lane >> 2;
    const int tig = lane & 3;

    float acc[2][4][4] = {};

    for (int kk = 0; kk < 256; kk += GBK) {
        #pragma unroll
        for (int j = 0; j < 2; j++) {
            int row = bm + arow + j * 64;
            float4 a4 = (row < M)
                ? *(const float4*)(feat + (size_t)row * 256 + kk + acol)
                : make_float4(0.f, 0.f, 0.f, 0.f);
            As[acol + 0][arow + j * 64] = f2tf32(a4.x);
            As[acol + 1][arow + j * 64] = f2tf32(a4.y);
            As[acol + 2][arow + j * 64] = f2tf32(a4.z);
            As[acol + 3][arow + j * 64] = f2tf32(a4.w);
        }
        {
            float4 b4 = *(const float4*)(W + (size_t)(bn + arow) * 256 + kk + acol);
            Bs[acol + 0][arow] = f2tf32(b4.x);
            Bs[acol + 1][arow] = f2tf32(b4.y);
            Bs[acol + 2][arow] = f2tf32(b4.z);
            Bs[acol + 3][arow] = f2tf32(b4.w);
        }
        __syncthreads();

        #pragma unroll
        for (int ks = 0; ks < GBK; ks += 8) {
            uint32_t af[2][4];
            #pragma unroll
            for (int mt = 0; mt < 2; mt++) {
                int r = warpM * 32 + mt * 16 + gid;
                af[mt][0] = As[ks + tig    ][r];
                af[mt][1] = As[ks + tig    ][r + 8];
                af[mt][2] = As[ks + tig + 4][r];
                af[mt][3] = As[ks + tig + 4][r + 8];
            }
            uint32_t bf[4][2];
            #pragma unroll
            for (int nt = 0; nt < 4; nt++) {
                int nidx = warpN * 32 + nt * 8 + gid;
                bf[nt][0] = Bs[ks + tig    ][nidx];
                bf[nt][1] = Bs[ks + tig + 4][nidx];
            }
            #pragma unroll
            for (int mt = 0; mt < 2; mt++)
                #pragma unroll
                for (int nt = 0; nt < 4; nt++)
                    mma_tf32(acc[mt][nt],
                             af[mt][0], af[mt][1], af[mt][2], af[mt][3],
                             bf[nt][0], bf[nt][1]);
        }
        __syncthreads();
    }

    #pragma unroll
    for (int mt = 0; mt < 2; mt++) {
        int row = bm + warpM * 32 + mt * 16 + gid;
        #pragma unroll
        for (int nt = 0; nt < 4; nt++) {
            int col = bn + warpN * 32 + nt * 8 + tig * 2;
            float b0 = bias[col], b1 = bias[col + 1];
            if (row < M) {
                float2 o = make_float2(acc[mt][nt][0] + b0, acc[mt][nt][1] + b1);
                *(float2*)(C + (size_t)row * 256 + col) = o;
            }
            if (row + 8 < M) {
                float2 o = make_float2(acc[mt][nt][2] + b0, acc[mt][nt][3] + b1);
                *(float2*)(C + (size_t)(row + 8) * 256 + col) = o;
            }
        }
    }
}

// ---------------------------------------------------------------------------
// fused dst-centric attention + gated skip + LN + PReLU.  one warp per node.
// Scores are tiny (|e| < ~0.6): exp without max-subtraction is exact-equivalent.
// lane owns features [lane*8, lane*8+8); head h = lane>>3.
// ---------------------------------------------------------------------------
__global__ __launch_bounds__(256) void fused_node(
    const float* __restrict__ Wg, const float* __restrict__ bg,
    const float* __restrict__ lnw, const float* __restrict__ lnb,
    const float* __restrict__ prelu_a, float* __restrict__ out, int N)
{
    int w    = (int)((blockIdx.x * 256u + threadIdx.x) >> 5);
    int lane = threadIdx.x & 31;
    if (w >= N) return;

    // k row for this dst node (stays in registers)
    const float4* kr = (const float4*)(g_k + (size_t)w * HD);
    float4 k0 = kr[lane * 2], k1 = kr[lane * 2 + 1];

    float acc[8] = {};
    float den = 0.0f;

    int beg = g_rowptr[w];
    int end = g_rowptr[w + 1];
    for (int j = beg; j < end; j++) {
        int s = g_cidx[j];
        const float4* qr = (const float4*)(g_q + (size_t)s * HD);
        float4 q0 = qr[lane * 2], q1 = qr[lane * 2 + 1];
        const float4* vr = (const float4*)(g_v + (size_t)s * HD);
        float4 v0 = vr[lane * 2], v1 = vr[lane * 2 + 1];

        float p = q0.x * k0.x + q0.y * k0.y + q0.z * k0.z + q0.w * k0.w
                + q1.x * k1.x + q1.y * k1.y + q1.z * k1.z + q1.w * k1.w;
        p += __shfl_xor_sync(0xffffffffu, p, 4);
        p += __shfl_xor_sync(0xffffffffu, p, 2);
        p += __shfl_xor_sync(0xffffffffu, p, 1);
        float ex = __expf(p * 0.125f);
        den += ex;

        acc[0] += ex * v0.x; acc[1] += ex * v0.y;
        acc[2] += ex * v0.z; acc[3] += ex * v0.w;
        acc[4] += ex * v1.x; acc[5] += ex * v1.y;
        acc[6] += ex * v1.z; acc[7] += ex * v1.w;
    }

    float inv = (den > 0.0f) ? (1.0f / den) : 0.0f;
    float rs[8];
    #pragma unroll
    for (int i = 0; i < 8; i++) rs[i] = acc[i] * inv;

    // skip row
    const float4* skp = (const float4*)(g_skip + (size_t)w * HD);
    float4 s0 = skp[lane * 2], s1 = skp[lane * 2 + 1];
    float sk[8] = {s0.x, s0.y, s0.z, s0.w, s1.x, s1.y, s1.z, s1.w};

    // gate = sigmoid([skip; rst; skip-rst] . Wg + bg)
    float gp = 0.0f;
    #pragma unroll
    for (int i = 0; i < 8; i++) {
        int c = lane * 8 + i;
        gp += sk[i] * Wg[c] + rs[i] * Wg[256 + c] + (sk[i] - rs[i]) * Wg[512 + c];
    }
    #pragma unroll
    for (int m = 16; m >= 1; m >>= 1) gp += __shfl_xor_sync(0xffffffffu, gp, m);
    float g = 1.0f / (1.0f + expf(-(gp + bg[0])));

    float x[8];
    float sum = 0.0f;
    #pragma unroll
    for (int i = 0; i < 8; i++) {
        x[i] = g * sk[i] + (1.0f - g) * rs[i];
        sum += x[i];
    }
    #pragma unroll
    for (int m = 16; m >= 1; m >>= 1) sum += __shfl_xor_sync(0xffffffffu, sum, m);
    float mu = sum * (1.0f / 256.0f);

    float vs = 0.0f;
    #pragma unroll
    for (int i = 0; i < 8; i++) {
        float dd = x[i] - mu;
        vs += dd * dd;
    }
    #pragma unroll
    for (int m = 16; m >= 1; m >>= 1) vs += __shfl_xor_sync(0xffffffffu, vs, m);
    float rstd = rsqrtf(vs * (1.0f / 256.0f) + 1e-5f);

    float a = *prelu_a;
    float o[8];
    #pragma unroll
    for (int i = 0; i < 8; i++) {
        int c = lane * 8 + i;
        float y = (x[i] - mu) * rstd * lnw[c] + lnb[c];
        o[i] = (y >= 0.0f) ? y : a * y;
    }
    float4* op = (float4*)(out + (size_t)w * HD);
    op[lane * 2]     = make_float4(o[0], o[1], o[2], o[3]);
    op[lane * 2 + 1] = make_float4(o[4], o[5], o[6], o[7]);
}

// ---------------------------------------------------------------------------
extern "C" void kernel_launch(void* const* d_in, const int* in_sizes, int n_in,
                              void* d_out, int out_size)
{
    const float* feat = (const float*)d_in[0];
    const int*   src  = (const int*)d_in[1];
    const int*   dst  = (const int*)d_in[2];
    const float* Wq = (const float*)d_in[3];  const float* bq = (const float*)d_in[4];
    const float* Wk = (const float*)d_in[5];  const float* bk = (const float*)d_in[6];
    const float* Wv = (const float*)d_in[7];  const float* bv = (const float*)d_in[8];
    const float* Ws = (const float*)d_in[9];  const float* bs = (const float*)d_in[10];
    const float* Wg = (const float*)d_in[11]; const float* bg = (const float*)d_in[12];
    const float* lnw = (const float*)d_in[13];
    const float* lnb = (const float*)d_in[14];
    const float* pa  = (const float*)d_in[15];
    float* out = (float*)d_out;

    int M = in_sizes[0] / HD;   // 50000
    int E = in_sizes[1];        // 800000
    if (M > NN) M = NN;
    if (E > EE) E = EE;

    // CSR build
    zero_deg<<<(M + 255) / 256, 256>>>(M);
    hist_kernel<<<(E + 255) / 256, 256>>>(dst, E);
    scan_kernel<<<1, 1024>>>(M);
    scatter_kernel<<<(E + 255) / 256, 256>>>(src, dst, E);

    // projections
    dim3 gg(HD / GBN, (M + GBM - 1) / GBM, 4);
    proj_gemm_tf32<<<gg, 256>>>(feat, Wq, bq, Wk, bk, Wv, bv, Ws, bs, M);

    // fused attention + epilogue (one warp per node)
    fused_node<<<(M + 7) / 8, 256>>>(Wg, bg, lnw, lnb, pa, out, M);
}

// round 5
// speedup vs baseline: 2.4718x; 1.2262x over previous
#include <cuda_runtime.h>
#include <math.h>
#include <stdint.h>

#define NN 50000
#define EE 800000
#define HD 256
#define NH 4
#define DH 64

// ---- static scratch (no allocations allowed) ----
__device__ float g_q[(size_t)NN * HD];
__device__ float g_k[(size_t)NN * HD];
__device__ float g_v[(size_t)NN * HD];
__device__ float g_skip[(size_t)NN * HD];
__device__ int   g_deg[NN];
__device__ int   g_rowptr[NN + 1];
__device__ int   g_cursor[NN];
__device__ int   g_cidx[EE];

// ---------------------------------------------------------------------------
// CSR build: zero degree -> histogram -> scan -> scatter
// ---------------------------------------------------------------------------
__global__ void zero_deg(int n) {
    int i = blockIdx.x * blockDim.x + threadIdx.x;
    if (i < n) g_deg[i] = 0;
}

__global__ void hist_kernel(const int* __restrict__ dst, int E) {
    int i = blockIdx.x * blockDim.x + threadIdx.x;
    if (i < E) atomicAdd(&g_deg[dst[i]], 1);
}

__global__ __launch_bounds__(1024) void scan_kernel(int n) {
    const int T = 1024;
    const int per = (NN + T - 1) / T;
    __shared__ int sm[T];
    int t = threadIdx.x;
    int base = t * per;
    int s = 0;
    for (int i = 0; i < per; i++) {
        int idx = base + i;
        if (idx < n) s += g_deg[idx];
    }
    sm[t] = s;
    __syncthreads();
    for (int off = 1; off < T; off <<= 1) {
        int v = (t >= off) ? sm[t - off] : 0;
        __syncthreads();
        sm[t] += v;
        __syncthreads();
    }
    int run = sm[t] - s;
    for (int i = 0; i < per; i++) {
        int idx = base + i;
        if (idx < n) {
            g_rowptr[idx] = run;
            g_cursor[idx] = run;
            run += g_deg[idx];
        }
    }
    if (t == T - 1) g_rowptr[n] = run;
}

__global__ void scatter_kernel(const int* __restrict__ src,
                               const int* __restrict__ dst, int E) {
    int i = blockIdx.x * blockDim.x + threadIdx.x;
    if (i < E) {
        int pos = atomicAdd(&g_cursor[dst[i]], 1);
        g_cidx[pos] = src[i];
    }
}

// ---------------------------------------------------------------------------
// tf32 / cp.async helpers
// ---------------------------------------------------------------------------
__device__ __forceinline__ uint32_t f2tf32(float x) {
    uint32_t r;
    asm("cvt.rna.tf32.f32 %0, %1;" : "=r"(r) : "f"(x));
    return r;
}

__device__ __forceinline__ void mma_tf32(float c[4],
    uint32_t a0, uint32_t a1, uint32_t a2, uint32_t a3,
    uint32_t b0, uint32_t b1)
{
    asm volatile(
        "mma.sync.aligned.m16n8k8.row.col.f32.tf32.tf32.f32 "
        "{%0,%1,%2,%3}, {%4,%5,%6,%7}, {%8,%9}, {%0,%1,%2,%3};\n"
        : "+f"(c[0]), "+f"(c[1]), "+f"(c[2]), "+f"(c[3])
        : "r"(a0), "r"(a1), "r"(a2), "r"(a3), "r"(b0), "r"(b1));
}

__device__ __forceinline__ void cp16(uint32_t saddr, const void* g, bool pred) {
    int sz = pred ? 16 : 0;
    asm volatile("cp.async.cg.shared.global [%0], [%1], 16, %2;"
        :: "r"(saddr), "l"(g), "r"(sz));
}
__device__ __forceinline__ void cp_commit() {
    asm volatile("cp.async.commit_group;");
}
template <int N>
__device__ __forceinline__ void cp_wait() {
    asm volatile("cp.async.wait_group %0;" :: "n"(N));
}

// ---------------------------------------------------------------------------
// 4 projections, tf32 tensor-core GEMM (NT): C = feat @ W^T + b
// BM=128, BN=64, BK=16, 256 threads (8 warps 4x2), warp tile 32x32.
// 3-stage cp.async pipeline; smem row-major fp32, stride 20 (conflict-free
// fragment loads: addr mod 32 = 20*gid + tig is a bank permutation).
// ---------------------------------------------------------------------------
#define GBM 128
#define GBN 64
#define GBK 16
#define NKT 16       // 256 / GBK
#define SSTR 20      // smem row stride (floats)

__global__ __launch_bounds__(256) void proj_gemm_tf32(
    const float* __restrict__ feat,
    const float* __restrict__ Wq, const float* __restrict__ bq,
    const float* __restrict__ Wk, const float* __restrict__ bk,
    const float* __restrict__ Wv, const float* __restrict__ bv,
    const float* __restrict__ Ws, const float* __restrict__ bs,
    int M)
{
    __shared__ float As[3][GBM][SSTR];
    __shared__ float Bs[3][GBN][SSTR];

    const float* W;
    const float* bias;
    float* C;
    switch (blockIdx.z) {
        case 0:  W = Wq; bias = bq; C = g_q;    break;
        case 1:  W = Wk; bias = bk; C = g_k;    break;
        case 2:  W = Wv; bias = bv; C = g_v;    break;
        default: W = Ws; bias = bs; C = g_skip; break;
    }

    const int tid   = threadIdx.x;
    const int lane  = tid & 31;
    const int warp  = tid >> 5;
    const int warpM = warp & 3;
    const int warpN = warp >> 2;
    const int bm = blockIdx.y * GBM;
    const int bn = blockIdx.x * GBN;

    const int gid = lane >> 2;
    const int tig = lane & 3;

    // copy assignments
    const int ar0 = tid >> 2;             // A rows: ar0 and ar0+64
    const int akc = (tid & 3) * 4;        // k chunk within tile
    const int br0 = tid >> 2;             // B row 0..63

    uint32_t sA = (uint32_t)__cvta_generic_to_shared(&As[0][0][0]);
    uint32_t sB = (uint32_t)__cvta_generic_to_shared(&Bs[0][0][0]);
    const uint32_t stageA = GBM * SSTR * 4;
    const uint32_t stageB = GBN * SSTR * 4;

    float acc[2][4][4] = {};

    auto load_stage = [&](int j, int st) {
        int kk = j * GBK;
        // A: two 16B chunks
        {
            int row = ar0;
            int grow = bm + row;
            cp16(sA + st * stageA + (row * SSTR + akc) * 4,
                 feat + (size_t)grow * 256 + kk + akc, grow < M);
            row = ar0 + 64;
            grow = bm + row;
            cp16(sA + st * stageA + (row * SSTR + akc) * 4,
                 feat + (size_t)grow * 256 + kk + akc, grow < M);
        }
        // B: one 16B chunk
        cp16(sB + st * stageB + (br0 * SSTR + akc) * 4,
             W + (size_t)(bn + br0) * 256 + kk + akc, true);
        cp_commit();
    };

    load_stage(0, 0);
    load_stage(1, 1);

    for (int i = 0; i < NKT; i++) {
        if (i + 1 < NKT) cp_wait<1>(); else cp_wait<0>();
        __syncthreads();

        int st = i % 3;
        #pragma unroll
        for (int ks = 0; ks < GBK; ks += 8) {
            uint32_t af[2][4];
            #pragma unroll
            for (int mt = 0; mt < 2; mt++) {
                int r = warpM * 32 + mt * 16 + gid;
                af[mt][0] = f2tf32(As[st][r    ][ks + tig    ]);
                af[mt][1] = f2tf32(As[st][r + 8][ks + tig    ]);
                af[mt][2] = f2tf32(As[st][r    ][ks + tig + 4]);
                af[mt][3] = f2tf32(As[st][r + 8][ks + tig + 4]);
            }
            uint32_t bf[4][2];
            #pragma unroll
            for (int nt = 0; nt < 4; nt++) {
                int nidx = warpN * 32 + nt * 8 + gid;
                bf[nt][0] = f2tf32(Bs[st][nidx][ks + tig    ]);
                bf[nt][1] = f2tf32(Bs[st][nidx][ks + tig + 4]);
            }
            #pragma unroll
            for (int mt = 0; mt < 2; mt++)
                #pragma unroll
                for (int nt = 0; nt < 4; nt++)
                    mma_tf32(acc[mt][nt],
                             af[mt][0], af[mt][1], af[mt][2], af[mt][3],
                             bf[nt][0], bf[nt][1]);
        }

        if (i + 2 < NKT) load_stage(i + 2, (i + 2) % 3);
    }

    #pragma unroll
    for (int mt = 0; mt < 2; mt++) {
        int row = bm + warpM * 32 + mt * 16 + gid;
        #pragma unroll
        for (int nt = 0; nt < 4; nt++) {
            int col = bn + warpN * 32 + nt * 8 + tig * 2;
            float b0 = bias[col], b1 = bias[col + 1];
            if (row < M) {
                float2 o = make_float2(acc[mt][nt][0] + b0, acc[mt][nt][1] + b1);
                *(float2*)(C + (size_t)row * 256 + col) = o;
            }
            if (row + 8 < M) {
                float2 o = make_float2(acc[mt][nt][2] + b0, acc[mt][nt][3] + b1);
                *(float2*)(C + (size_t)(row + 8) * 256 + col) = o;
            }
        }
    }
}

// ---------------------------------------------------------------------------
// fused dst-centric attention + gated skip + LN + PReLU.  one warp per node.
// Scores are tiny (|e| < ~0.6): exp without max-subtraction is exact-equivalent.
// ---------------------------------------------------------------------------
__global__ __launch_bounds__(256) void fused_node(
    const float* __restrict__ Wg, const float* __restrict__ bg,
    const float* __restrict__ lnw, const float* __restrict__ lnb,
    const float* __restrict__ prelu_a, float* __restrict__ out, int N)
{
    int w    = (int)((blockIdx.x * 256u + threadIdx.x) >> 5);
    int lane = threadIdx.x & 31;
    if (w >= N) return;

    const float4* kr = (const float4*)(g_k + (size_t)w * HD);
    float4 k0 = kr[lane * 2], k1 = kr[lane * 2 + 1];

    float acc[8] = {};
    float den = 0.0f;

    int beg = g_rowptr[w];
    int end = g_rowptr[w + 1];
    for (int j = beg; j < end; j++) {
        int s = g_cidx[j];
        const float4* qr = (const float4*)(g_q + (size_t)s * HD);
        float4 q0 = qr[lane * 2], q1 = qr[lane * 2 + 1];
        const float4* vr = (const float4*)(g_v + (size_t)s * HD);
        float4 v0 = vr[lane * 2], v1 = vr[lane * 2 + 1];

        float p = q0.x * k0.x + q0.y * k0.y + q0.z * k0.z + q0.w * k0.w
                + q1.x * k1.x + q1.y * k1.y + q1.z * k1.z + q1.w * k1.w;
        p += __shfl_xor_sync(0xffffffffu, p, 4);
        p += __shfl_xor_sync(0xffffffffu, p, 2);
        p += __shfl_xor_sync(0xffffffffu, p, 1);
        float ex = __expf(p * 0.125f);
        den += ex;

        acc[0] += ex * v0.x; acc[1] += ex * v0.y;
        acc[2] += ex * v0.z; acc[3] += ex * v0.w;
        acc[4] += ex * v1.x; acc[5] += ex * v1.y;
        acc[6] += ex * v1.z; acc[7] += ex * v1.w;
    }

    float inv = (den > 0.0f) ? (1.0f / den) : 0.0f;
    float rs[8];
    #pragma unroll
    for (int i = 0; i < 8; i++) rs[i] = acc[i] * inv;

    const float4* skp = (const float4*)(g_skip + (size_t)w * HD);
    float4 s0 = skp[lane * 2], s1 = skp[lane * 2 + 1];
    float sk[8] = {s0.x, s0.y, s0.z, s0.w, s1.x, s1.y, s1.z, s1.w};

    float gp = 0.0f;
    #pragma unroll
    for (int i = 0; i < 8; i++) {
        int c = lane * 8 + i;
        gp += sk[i] * Wg[c] + rs[i] * Wg[256 + c] + (sk[i] - rs[i]) * Wg[512 + c];
    }
    #pragma unroll
    for (int m = 16; m >= 1; m >>= 1) gp += __shfl_xor_sync(0xffffffffu, gp, m);
    float g = 1.0f / (1.0f + expf(-(gp + bg[0])));

    float x[8];
    float sum = 0.0f;
    #pragma unroll
    for (int i = 0; i < 8; i++) {
        x[i] = g * sk[i] + (1.0f - g) * rs[i];
        sum += x[i];
    }
    #pragma unroll
    for (int m = 16; m >= 1; m >>= 1) sum += __shfl_xor_sync(0xffffffffu, sum, m);
    float mu = sum * (1.0f / 256.0f);

    float vs = 0.0f;
    #pragma unroll
    for (int i = 0; i < 8; i++) {
        float dd = x[i] - mu;
        vs += dd * dd;
    }
    #pragma unroll
    for (int m = 16; m >= 1; m >>= 1) vs += __shfl_xor_sync(0xffffffffu, vs, m);
    float rstd = rsqrtf(vs * (1.0f / 256.0f) + 1e-5f);

    float a = *prelu_a;
    float o[8];
    #pragma unroll
    for (int i = 0; i < 8; i++) {
        int c = lane * 8 + i;
        float y = (x[i] - mu) * rstd * lnw[c] + lnb[c];
        o[i] = (y >= 0.0f) ? y : a * y;
    }
    float4* op = (float4*)(out + (size_t)w * HD);
    op[lane * 2]     = make_float4(o[0], o[1], o[2], o[3]);
    op[lane * 2 + 1] = make_float4(o[4], o[5], o[6], o[7]);
}

// ---------------------------------------------------------------------------
extern "C" void kernel_launch(void* const* d_in, const int* in_sizes, int n_in,
                              void* d_out, int out_size)
{
    const float* feat = (const float*)d_in[0];
    const int*   src  = (const int*)d_in[1];
    const int*   dst  = (const int*)d_in[2];
    const float* Wq = (const float*)d_in[3];  const float* bq = (const float*)d_in[4];
    const float* Wk = (const float*)d_in[5];  const float* bk = (const float*)d_in[6];
    const float* Wv = (const float*)d_in[7];  const float* bv = (const float*)d_in[8];
    const float* Ws = (const float*)d_in[9];  const float* bs = (const float*)d_in[10];
    const float* Wg = (const float*)d_in[11]; const float* bg = (const float*)d_in[12];
    const float* lnw = (const float*)d_in[13];
    const float* lnb = (const float*)d_in[14];
    const float* pa  = (const float*)d_in[15];
    float* out = (float*)d_out;

    int M = in_sizes[0] / HD;   // 50000
    int E = in_sizes[1];        // 800000
    if (M > NN) M = NN;
    if (E > EE) E = EE;

    // CSR build
    zero_deg<<<(M + 255) / 256, 256>>>(M);
    hist_kernel<<<(E + 255) / 256, 256>>>(dst, E);
    scan_kernel<<<1, 1024>>>(M);
    scatter_kernel<<<(E + 255) / 256, 256>>>(src, dst, E);

    // projections
    dim3 gg(HD / GBN, (M + GBM - 1) / GBM, 4);
    proj_gemm_tf32<<<gg, 256>>>(feat, Wq, bq, Wk, bk, Wv, bv, Ws, bs, M);

    // fused attention + epilogue (one warp per node)
    fused_node<<<(M + 7) / 8, 256>>>(Wg, bg, lnw, lnb, pa, out, M);
}